// round 4
// baseline (speedup 1.0000x reference)
#include <cuda_runtime.h>
#include <cstdint>

typedef unsigned long long ULL;

#define NTOK 1024
#define CQ   768
#define CZ   128
#define NH   16
#define HD   48
#define HDQ  768
#define QSCALE 0.14433756729740643f  // 1/sqrt(48)

// ---------------- f32x2 packed helpers ----------------
__device__ __forceinline__ ULL fma2(ULL a, ULL b, ULL c) {
    ULL d; asm("fma.rn.f32x2 %0, %1, %2, %3;" : "=l"(d) : "l"(a), "l"(b), "l"(c)); return d;
}
__device__ __forceinline__ ULL add2(ULL a, ULL b) {
    ULL d; asm("add.rn.f32x2 %0, %1, %2;" : "=l"(d) : "l"(a), "l"(b)); return d;
}
__device__ __forceinline__ ULL mul2(ULL a, ULL b) {
    ULL d; asm("mul.rn.f32x2 %0, %1, %2;" : "=l"(d) : "l"(a), "l"(b)); return d;
}
__device__ __forceinline__ ULL pack2(float lo, float hi) {
    ULL d; asm("mov.b64 %0, {%1, %2};" : "=l"(d) : "f"(lo), "f"(hi)); return d;
}
__device__ __forceinline__ float lo2(ULL u){ return __uint_as_float((unsigned)u); }
__device__ __forceinline__ float hi2(ULL u){ return __uint_as_float((unsigned)(u >> 32)); }

// ---------------- scratch ----------------
__device__ float g_an[NTOK * CQ];
__device__ float g_bias[(size_t)NH * NTOK * NTOK];   // pair bias (read-only after k_pair_bias)
__device__ float g_q[NH * NTOK * HD];
__device__ float g_kT[NH * HD * NTOK];
__device__ float g_v[NH * NTOK * HD];
__device__ float g_gate[NTOK * HDQ];
__device__ float g_og[NTOK * HDQ];

// ---------------- LayerNorm of a ----------------
__global__ void k_ln_a(const float* __restrict__ a, const float* __restrict__ g,
                       const float* __restrict__ b) {
    int row = blockIdx.x, tid = threadIdx.x;
    const float* x = a + (size_t)row * CQ;
    float v0 = x[tid], v1 = x[tid + 256], v2 = x[tid + 512];
    float s = v0 + v1 + v2;
    float ss = v0*v0 + v1*v1 + v2*v2;
    __shared__ float sm[8], sm2[8];
    #pragma unroll
    for (int o = 16; o; o >>= 1) {
        s  += __shfl_xor_sync(0xffffffffu, s, o);
        ss += __shfl_xor_sync(0xffffffffu, ss, o);
    }
    if ((tid & 31) == 0) { sm[tid >> 5] = s; sm2[tid >> 5] = ss; }
    __syncthreads();
    if (tid == 0) {
        float S = 0, SS = 0;
        for (int i = 0; i < 8; i++) { S += sm[i]; SS += sm2[i]; }
        float mu = S * (1.0f / CQ);
        float var = SS * (1.0f / CQ) - mu * mu;
        sm[0] = mu; sm2[0] = rsqrtf(var + 1e-5f);
    }
    __syncthreads();
    float mu = sm[0], rstd = sm2[0];
    float* o = g_an + (size_t)row * CQ;
    o[tid]       = (v0 - mu) * rstd * g[tid]       + b[tid];
    o[tid + 256] = (v1 - mu) * rstd * g[tid + 256] + b[tid + 256];
    o[tid + 512] = (v2 - mu) * rstd * g[tid + 512] + b[tid + 512];
}

// ---------------- pair bias (R2 version) ----------------
#define PB_SMEM_FLOATS (2*256*32 + 2048 + 32)
__global__ __launch_bounds__(256, 2)
void k_pair_bias(const float* __restrict__ z, const float* __restrict__ gz,
                 const float* __restrict__ bz, const float* __restrict__ wz) {
    extern __shared__ float sm[];
    float* zb    = sm;
    float* wps   = sm + 16384;
    float* cs_cb = wps + 2048;

    int tid = threadIdx.x;
    for (int i = tid; i < CZ * NH; i += 256) {
        int c = i >> 4, h = i & 15;
        wps[(c >> 1) * 32 + h * 2 + (c & 1)] = gz[c] * wz[c * NH + h];
    }
    __syncthreads();
    if (tid < 16) {
        float cs = 0.f, cb = 0.f;
        for (int c = 0; c < CZ; c++) {
            cs += wps[(c >> 1) * 32 + tid * 2 + (c & 1)];
            cb += bz[c] * wz[c * NH + tid];
        }
        cs_cb[tid] = cs; cs_cb[16 + tid] = cb;
    }
    __syncthreads();

    int tile = blockIdx.x;
    const float4* zg = (const float4*)(z + (size_t)tile * 256 * CZ);

    int srow[8], sf[8];
    #pragma unroll
    for (int j = 0; j < 8; j++) { int i = tid + j * 256; srow[j] = i >> 3; sf[j] = i & 7; }

    float4 pre[8];
    #pragma unroll
    for (int j = 0; j < 8; j++)
        pre[j] = zg[(size_t)srow[j] * 32 + sf[j]];

    ULL acc[NH];
    #pragma unroll
    for (int h = 0; h < NH; h++) acc[h] = 0ULL;
    ULL sum2 = 0ULL, ss2 = 0ULL;

    for (int c = 0; c < 4; c++) {
        float* buf = zb + (c & 1) * 8192;
        #pragma unroll
        for (int j = 0; j < 8; j++)
            *(float4*)(buf + srow[j] * 32 + ((sf[j] + srow[j]) & 7) * 4) = pre[j];
        __syncthreads();
        if (c < 3) {
            #pragma unroll
            for (int j = 0; j < 8; j++)
                pre[j] = zg[(size_t)srow[j] * 32 + (c + 1) * 8 + sf[j]];
        }
        #pragma unroll
        for (int j = 0; j < 8; j++) {
            int pos = (j + tid) & 7;
            float4 zv = *(const float4*)(buf + tid * 32 + pos * 4);
            ULL z01 = ((const ULL*)&zv)[0];
            ULL z23 = ((const ULL*)&zv)[1];
            sum2 = add2(sum2, add2(z01, z23));
            ss2  = fma2(z01, z01, fma2(z23, z23, ss2));
            int p0 = c * 16 + 2 * j;
            const float4* w0 = (const float4*)(wps + p0 * 32);
            const float4* w1 = (const float4*)(wps + p0 * 32 + 32);
            #pragma unroll
            for (int h2 = 0; h2 < 8; h2++) {
                float4 wa = w0[h2];
                float4 wb = w1[h2];
                acc[2*h2]     = fma2(z01, ((const ULL*)&wa)[0], acc[2*h2]);
                acc[2*h2 + 1] = fma2(z01, ((const ULL*)&wa)[1], acc[2*h2 + 1]);
                acc[2*h2]     = fma2(z23, ((const ULL*)&wb)[0], acc[2*h2]);
                acc[2*h2 + 1] = fma2(z23, ((const ULL*)&wb)[1], acc[2*h2 + 1]);
            }
        }
        __syncthreads();
    }

    float sum = lo2(sum2) + hi2(sum2);
    float ss  = lo2(ss2)  + hi2(ss2);
    float mu  = sum * (1.0f / CZ);
    float var = ss * (1.0f / CZ) - mu * mu;
    float rstd = rsqrtf(var + 1e-5f);

    float* outs = zb;
    #pragma unroll
    for (int h = 0; h < NH; h++) {
        float d = lo2(acc[h]) + hi2(acc[h]);
        outs[h * 256 + tid] = rstd * (d - mu * cs_cb[h]) + cs_cb[16 + h];
    }
    __syncthreads();
    #pragma unroll
    for (int it = 0; it < 4; it++) {
        int idx = tid + it * 256;
        int h = idx >> 6, j4 = idx & 63;
        float4 v = *(const float4*)(outs + h * 256 + j4 * 4);
        *(float4*)(g_bias + ((size_t)h << 20) + (size_t)tile * 256 + j4 * 4) = v;
    }
}

// ---------------- SGEMM 64x128 (qkvg) ----------------
#define SA_STR 36
#define SB_STR 132
__device__ __forceinline__ void sgemm64x128(
    const float* __restrict__ A, const float* __restrict__ B,
    int K, int ldA, int ldB, int row0, int col0,
    float* sA, float* sB, ULL acc[4][4])
{
    int tid = threadIdx.x;
    int tm = (tid >> 4) << 2;
    int tn8 = (tid & 15) << 3;
    #pragma unroll
    for (int i = 0; i < 4; i++)
        #pragma unroll
        for (int j = 0; j < 4; j++) acc[i][j] = 0ULL;

    int ar[2], akq[2], br[4], bn[4];
    #pragma unroll
    for (int j = 0; j < 2; j++) { int fi = tid + j * 256; ar[j] = fi >> 3; akq[j] = fi & 7; }
    #pragma unroll
    for (int j = 0; j < 4; j++) { int fi = tid + j * 256; br[j] = fi >> 5; bn[j] = fi & 31; }

    float4 pa[2], pb[4];
    #pragma unroll
    for (int j = 0; j < 2; j++)
        pa[j] = *(const float4*)(A + (size_t)(row0 + ar[j]) * ldA + akq[j] * 4);
    #pragma unroll
    for (int j = 0; j < 4; j++)
        pb[j] = *(const float4*)(B + (size_t)br[j] * ldB + col0 + bn[j] * 4);

    for (int k0 = 0; k0 < K; k0 += 32) {
        #pragma unroll
        for (int j = 0; j < 2; j++)
            *(float4*)(sA + ar[j] * SA_STR + akq[j] * 4) = pa[j];
        #pragma unroll
        for (int j = 0; j < 4; j++)
            *(float4*)(sB + br[j] * SB_STR + bn[j] * 4) = pb[j];
        __syncthreads();
        if (k0 + 32 < K) {
            #pragma unroll
            for (int j = 0; j < 2; j++)
                pa[j] = *(const float4*)(A + (size_t)(row0 + ar[j]) * ldA + k0 + 32 + akq[j] * 4);
            #pragma unroll
            for (int j = 0; j < 4; j++)
                pb[j] = *(const float4*)(B + (size_t)(k0 + 32 + br[j]) * ldB + col0 + bn[j] * 4);
        }
        #pragma unroll 8
        for (int kk = 0; kk < 32; kk++) {
            float4 b0 = *(const float4*)(sB + kk * SB_STR + tn8);
            float4 b1 = *(const float4*)(sB + kk * SB_STR + tn8 + 4);
            ULL bl0 = ((const ULL*)&b0)[0], bh0 = ((const ULL*)&b0)[1];
            ULL bl1 = ((const ULL*)&b1)[0], bh1 = ((const ULL*)&b1)[1];
            #pragma unroll
            for (int i = 0; i < 4; i++) {
                float a = sA[(tm + i) * SA_STR + kk];
                ULL a2 = pack2(a, a);
                acc[i][0] = fma2(a2, bl0, acc[i][0]);
                acc[i][1] = fma2(a2, bh0, acc[i][1]);
                acc[i][2] = fma2(a2, bl1, acc[i][2]);
                acc[i][3] = fma2(a2, bh1, acc[i][3]);
            }
        }
        __syncthreads();
    }
}

__global__ __launch_bounds__(256)
void k_qkvg(const float* __restrict__ wq, const float* __restrict__ wk,
            const float* __restrict__ wv, const float* __restrict__ wg,
            const float* __restrict__ bg) {
    __shared__ float sA[64 * SA_STR], sB[32 * SB_STR];
    ULL acc[4][4];
    int mode = blockIdx.z;
    const float* B = (mode == 0) ? wq : (mode == 1) ? wk : (mode == 2) ? wv : wg;
    int row0 = blockIdx.y * 64, col0 = blockIdx.x * 128;
    sgemm64x128(g_an, B, CQ, CQ, HDQ, row0, col0, sA, sB, acc);

    int tid = threadIdx.x;
    int tm = (tid >> 4) << 2, tn8 = (tid & 15) << 3;
    #pragma unroll
    for (int i = 0; i < 4; i++) {
        int row = row0 + tm + i;
        #pragma unroll
        for (int j = 0; j < 8; j++) {
            int col = col0 + tn8 + j;
            float v = (j & 1) ? hi2(acc[i][j >> 1]) : lo2(acc[i][j >> 1]);
            int h = col / HD, d = col - h * HD;
            if (mode == 0)      g_q [((size_t)h * NTOK + row) * HD + d] = v * QSCALE;
            else if (mode == 1) g_kT[((size_t)h * HD + d) * NTOK + row] = v;
            else if (mode == 2) g_v [((size_t)h * NTOK + row) * HD + d] = v;
            else                g_gate[(size_t)row * HDQ + col] = 1.f / (1.f + __expf(-(v + bg[col])));
        }
    }
}

// ---------------- flash attention: 32 q-rows per block, online softmax ----------------
#define FKT_STR 68
#define FV_STR  68
#define FP_STR  68
// smem floats: sQ 1536 | sKt 48*68=3264 | sV 64*68=4352 | sP 32*68=2176 | sMask 32
#define FL_Q   0
#define FL_KT  1536
#define FL_V   (FL_KT + 48*FKT_STR)
#define FL_P   (FL_V + 64*FV_STR)
#define FL_MSK (FL_P + 32*FP_STR)
#define FL_SMEM_FLOATS (FL_MSK + 32)

__global__ __launch_bounds__(256)
void k_flash(const float* __restrict__ mask) {
    extern __shared__ float sm[];
    float* sQ  = sm + FL_Q;
    float* sKt = sm + FL_KT;
    float* sV  = sm + FL_V;
    float* sP  = sm + FL_P;
    float* sMk = sm + FL_MSK;

    int h = blockIdx.y, qt = blockIdx.x, tid = threadIdx.x;
    int row0 = qt * 32;
    int qg = tid >> 4;          // 16 groups of 2 rows
    int cg = tid & 15;          // 16 groups of 4 cols
    int r0 = qg * 2;
    int c04 = cg * 4;

    // stage Q tile (32x48) and mask rows; zero sV pad cols once
    const float* Q = g_q + ((size_t)h * NTOK + row0) * HD;
    for (int fi = tid; fi < 32 * 12; fi += 256) {
        int r = fi / 12, c = fi - r * 12;
        *(float4*)(sQ + r * HD + c * 4) = *(const float4*)(Q + r * HD + c * 4);
    }
    if (tid < 32) sMk[tid] = mask[row0 + tid];
    { int r = tid >> 2, c = tid & 3;
      *(float4*)(sV + r * FV_STR + 48 + c * 4) = make_float4(0.f,0.f,0.f,0.f); }

    const float* biasBase = g_bias + ((size_t)h << 20);
    const float* Vh = g_v + (size_t)h * NTOK * HD;

    float m_i[2] = {-1e30f, -1e30f};
    float l_i[2] = {0.f, 0.f};
    ULL O[2][2] = {{0ULL,0ULL},{0ULL,0ULL}};

    for (int t = 0; t < 16; t++) {
        __syncthreads();
        // stage Kt (48x64) from g_kT, V (64x48) from g_v
        #pragma unroll
        for (int j = 0; j < 3; j++) {
            int fi = tid + j * 256;               // < 768
            int d = fi >> 4, c = fi & 15;
            float4 v = *(const float4*)(g_kT + ((size_t)h * HD + d) * NTOK + t * 64 + c * 4);
            *(float4*)(sKt + d * FKT_STR + c * 4) = v;
        }
        #pragma unroll
        for (int j = 0; j < 3; j++) {
            int fi = tid + j * 256;               // < 768
            int r = fi / 12, c = fi - r * 12;
            float4 v = *(const float4*)(Vh + (size_t)(t * 64 + r) * HD + c * 4);
            *(float4*)(sV + r * FV_STR + c * 4) = v;
        }
        __syncthreads();

        // S tile: 2 rows x 4 cols per thread
        ULL acc[2][2] = {{0ULL,0ULL},{0ULL,0ULL}};
        #pragma unroll 6
        for (int d = 0; d < HD; d++) {
            float4 kv = *(const float4*)(sKt + d * FKT_STR + c04);
            ULL k01 = ((const ULL*)&kv)[0], k23 = ((const ULL*)&kv)[1];
            float q0 = sQ[r0 * HD + d], q1 = sQ[(r0 + 1) * HD + d];
            ULL q0d = pack2(q0, q0), q1d = pack2(q1, q1);
            acc[0][0] = fma2(q0d, k01, acc[0][0]);
            acc[0][1] = fma2(q0d, k23, acc[0][1]);
            acc[1][0] = fma2(q1d, k01, acc[1][0]);
            acc[1][1] = fma2(q1d, k23, acc[1][1]);
        }

        int colb = t * 64 + c04;
        float4 mc = *(const float4*)(mask + colb);
        #pragma unroll
        for (int i = 0; i < 2; i++) {
            int r = r0 + i, grow = row0 + r;
            float mr = sMk[r];
            float4 bv = *(const float4*)(biasBase + (size_t)grow * NTOK + colb);
            float4 s;
            s.x = lo2(acc[i][0]) + bv.x + 1e9f * (mr * mc.x - 1.f);
            s.y = hi2(acc[i][0]) + bv.y + 1e9f * (mr * mc.y - 1.f);
            s.z = lo2(acc[i][1]) + bv.z + 1e9f * (mr * mc.z - 1.f);
            s.w = hi2(acc[i][1]) + bv.w + 1e9f * (mr * mc.w - 1.f);
            float cm = fmaxf(fmaxf(s.x, s.y), fmaxf(s.z, s.w));
            #pragma unroll
            for (int off = 8; off; off >>= 1)
                cm = fmaxf(cm, __shfl_xor_sync(0xffffffffu, cm, off));
            float nm = fmaxf(m_i[i], cm);
            float sc = __expf(m_i[i] - nm);
            float4 p;
            p.x = __expf(s.x - nm); p.y = __expf(s.y - nm);
            p.z = __expf(s.z - nm); p.w = __expf(s.w - nm);
            float ps = p.x + p.y + p.z + p.w;
            #pragma unroll
            for (int off = 8; off; off >>= 1)
                ps += __shfl_xor_sync(0xffffffffu, ps, off);
            l_i[i] = l_i[i] * sc + ps;
            m_i[i] = nm;
            ULL sc2 = pack2(sc, sc);
            O[i][0] = mul2(O[i][0], sc2);
            O[i][1] = mul2(O[i][1], sc2);
            *(float4*)(sP + r * FP_STR + c04) = p;
        }
        __syncthreads();

        // PV: O += P(32x64) @ V(64x64padded), same thread mapping
        #pragma unroll 8
        for (int kk = 0; kk < 64; kk++) {
            float4 v4 = *(const float4*)(sV + kk * FV_STR + c04);
            ULL v01 = ((const ULL*)&v4)[0], v23 = ((const ULL*)&v4)[1];
            float p0 = sP[r0 * FP_STR + kk], p1 = sP[(r0 + 1) * FP_STR + kk];
            ULL p0d = pack2(p0, p0), p1d = pack2(p1, p1);
            O[0][0] = fma2(p0d, v01, O[0][0]);
            O[0][1] = fma2(p0d, v23, O[0][1]);
            O[1][0] = fma2(p1d, v01, O[1][0]);
            O[1][1] = fma2(p1d, v23, O[1][1]);
        }
    }

    if (c04 < HD) {
        #pragma unroll
        for (int i = 0; i < 2; i++) {
            int grow = row0 + r0 + i;
            float inv = 1.f / l_i[i];
            size_t idx = (size_t)grow * HDQ + h * HD + c04;
            float4 g4 = *(const float4*)(g_gate + idx);
            float4 o;
            o.x = lo2(O[i][0]) * inv * g4.x;
            o.y = hi2(O[i][0]) * inv * g4.y;
            o.z = lo2(O[i][1]) * inv * g4.z;
            o.w = hi2(O[i][1]) * inv * g4.w;
            *(float4*)(g_og + idx) = o;
        }
    }
}

// ---------------- SGEMM 64x64 core (k_out) ----------------
__device__ __forceinline__ void sgemm_core(
    const float* __restrict__ A, const float* __restrict__ B,
    int K, int ldA, int ldB,
    int row0, int col0, float* sA, float* sB, ULL acc[4][2])
{
    int tid = threadIdx.x;
    int tm = (tid >> 4) << 2;
    int tn = (tid & 15) << 2;
    int ar = tid >> 2,  ak = (tid & 3) << 2;
    int bk = tid >> 4,  bn = (tid & 15) << 2;
    #pragma unroll
    for (int i = 0; i < 4; i++) { acc[i][0] = 0ULL; acc[i][1] = 0ULL; }

    for (int k0 = 0; k0 < K; k0 += 16) {
        float4 av = *(const float4*)(A + (size_t)(row0 + ar) * ldA + (k0 + ak));
        float4 bv = *(const float4*)(B + (size_t)(k0 + bk) * ldB + (col0 + bn));
        *(float4*)(sA + ar * 20 + ak) = av;
        *(float4*)(sB + bk * 64 + bn) = bv;
        __syncthreads();
        #pragma unroll
        for (int kk = 0; kk < 16; kk++) {
            float4 b4 = *(const float4*)(sB + kk * 64 + tn);
            ULL b01 = ((const ULL*)&b4)[0];
            ULL b23 = ((const ULL*)&b4)[1];
            #pragma unroll
            for (int i = 0; i < 4; i++) {
                float a = sA[(tm + i) * 20 + kk];
                ULL a2 = pack2(a, a);
                acc[i][0] = fma2(a2, b01, acc[i][0]);
                acc[i][1] = fma2(a2, b23, acc[i][1]);
            }
        }
        __syncthreads();
    }
}

__global__ __launch_bounds__(256)
void k_out(const float* __restrict__ wo, const float* __restrict__ bo,
           float* __restrict__ out) {
    __shared__ float sA[64 * 20], sB[16 * 64];
    ULL acc[4][2];
    int row0 = blockIdx.y * 64, col0 = blockIdx.x * 64;
    sgemm_core(g_og, wo, CQ, CQ, CQ, row0, col0, sA, sB, acc);

    int tid = threadIdx.x;
    int tm = (tid >> 4) << 2, tn = (tid & 15) << 2;
    float4 bv = *(const float4*)(bo + col0 + tn);
    #pragma unroll
    for (int i = 0; i < 4; i++) {
        int row = row0 + tm + i;
        float4 r;
        r.x = lo2(acc[i][0]) + bv.x;
        r.y = hi2(acc[i][0]) + bv.y;
        r.z = lo2(acc[i][1]) + bv.z;
        r.w = hi2(acc[i][1]) + bv.w;
        *(float4*)(out + (size_t)row * CQ + col0 + tn) = r;
    }
}

// ---------------- launch ----------------
extern "C" void kernel_launch(void* const* d_in, const int* in_sizes, int n_in,
                              void* d_out, int out_size) {
    const float* a    = (const float*)d_in[0];
    const float* z    = (const float*)d_in[1];
    const float* mask = (const float*)d_in[2];
    const float* ga   = (const float*)d_in[3];
    const float* ba   = (const float*)d_in[4];
    const float* gz   = (const float*)d_in[5];
    const float* bz   = (const float*)d_in[6];
    const float* wz   = (const float*)d_in[7];
    const float* wq   = (const float*)d_in[8];
    const float* wk   = (const float*)d_in[9];
    const float* wv   = (const float*)d_in[10];
    const float* wg   = (const float*)d_in[11];
    const float* bg   = (const float*)d_in[12];
    const float* wo   = (const float*)d_in[13];
    const float* bo   = (const float*)d_in[14];
    float* out = (float*)d_out;

    cudaFuncSetAttribute(k_pair_bias, cudaFuncAttributeMaxDynamicSharedMemorySize,
                         PB_SMEM_FLOATS * 4);
    cudaFuncSetAttribute(k_flash, cudaFuncAttributeMaxDynamicSharedMemorySize,
                         FL_SMEM_FLOATS * 4);

    k_pair_bias<<<4096, 256, PB_SMEM_FLOATS * 4>>>(z, gz, bz, wz);
    k_ln_a<<<1024, 256>>>(a, ga, ba);
    k_qkvg<<<dim3(6, 16, 4), 256>>>(wq, wk, wv, wg, bg);
    k_flash<<<dim3(32, NH), 256, FL_SMEM_FLOATS * 4>>>(mask);
    k_out<<<dim3(12, 16), 256>>>(wo, bo, out);
}

// round 7
// speedup vs baseline: 1.2066x; 1.2066x over previous
#include <cuda_runtime.h>
#include <cuda_bf16.h>
#include <cstdint>

typedef unsigned long long ULL;
typedef __nv_bfloat16 bf16;

#define NTOK 1024
#define CQ   768
#define CZ   128
#define NH   16
#define HD   48
#define HDQ  768
#define QSCALE 0.14433756729740643f  // 1/sqrt(48)

// ================= f32x2 helpers (pair_bias) =================
__device__ __forceinline__ ULL fma2(ULL a, ULL b, ULL c) {
    ULL d; asm("fma.rn.f32x2 %0, %1, %2, %3;" : "=l"(d) : "l"(a), "l"(b), "l"(c)); return d;
}
__device__ __forceinline__ ULL add2(ULL a, ULL b) {
    ULL d; asm("add.rn.f32x2 %0, %1, %2;" : "=l"(d) : "l"(a), "l"(b)); return d;
}
__device__ __forceinline__ float lo2(ULL u){ return __uint_as_float((unsigned)u); }
__device__ __forceinline__ float hi2(ULL u){ return __uint_as_float((unsigned)(u >> 32)); }

// ================= mma.sync helpers =================
__device__ __forceinline__ uint32_t s2u(const void* p){
    uint32_t a; asm("{ .reg .u64 t; cvta.to.shared.u64 t, %1; cvt.u32.u64 %0, t; }" : "=r"(a) : "l"(p));
    return a;
}
__device__ __forceinline__ void ldsm4(uint32_t* r, uint32_t addr){
    asm volatile("ldmatrix.sync.aligned.m8n8.x4.shared.b16 {%0,%1,%2,%3}, [%4];"
        : "=r"(r[0]), "=r"(r[1]), "=r"(r[2]), "=r"(r[3]) : "r"(addr));
}
__device__ __forceinline__ void mma16816(float* c, uint32_t a0, uint32_t a1, uint32_t a2, uint32_t a3,
                                         uint32_t b0, uint32_t b1){
    asm volatile("mma.sync.aligned.m16n8k16.row.col.f32.bf16.bf16.f32 "
        "{%0,%1,%2,%3}, {%4,%5,%6,%7}, {%8,%9}, {%0,%1,%2,%3};"
        : "+f"(c[0]), "+f"(c[1]), "+f"(c[2]), "+f"(c[3])
        : "r"(a0), "r"(a1), "r"(a2), "r"(a3), "r"(b0), "r"(b1));
}

// ================= scratch =================
__device__ float g_bias[(size_t)NH * NTOK * NTOK];
__device__ bf16  g_anh[NTOK * CQ], g_anl[NTOK * CQ];
__device__ bf16  g_wTh[5u * CQ * CQ], g_wTl[5u * CQ * CQ];   // q,k,v,g,o transposed splits [n][k]
__device__ bf16  g_qh[NH * NTOK * HD], g_ql[NH * NTOK * HD];
__device__ bf16  g_kh[NH * NTOK * HD], g_kl[NH * NTOK * HD];
__device__ bf16  g_vth[NH * HD * NTOK], g_vtl[NH * HD * NTOK]; // [h][d][tok]
__device__ bf16  g_ph[(size_t)NH * NTOK * NTOK], g_pl[(size_t)NH * NTOK * NTOK];
__device__ float g_gate[NTOK * HDQ];
__device__ bf16  g_ogh[NTOK * HDQ], g_ogl[NTOK * HDQ];

// ================= LayerNorm of a -> bf16 splits =================
__global__ void k_ln_a(const float* __restrict__ a, const float* __restrict__ g,
                       const float* __restrict__ b) {
    int row = blockIdx.x, tid = threadIdx.x;
    const float* x = a + (size_t)row * CQ;
    float v0 = x[tid], v1 = x[tid + 256], v2 = x[tid + 512];
    float s = v0 + v1 + v2;
    float ss = v0*v0 + v1*v1 + v2*v2;
    __shared__ float sred[8], sred2[8];
    #pragma unroll
    for (int o = 16; o; o >>= 1) {
        s  += __shfl_xor_sync(0xffffffffu, s, o);
        ss += __shfl_xor_sync(0xffffffffu, ss, o);
    }
    if ((tid & 31) == 0) { sred[tid >> 5] = s; sred2[tid >> 5] = ss; }
    __syncthreads();
    if (tid == 0) {
        float S = 0, SS = 0;
        for (int i = 0; i < 8; i++) { S += sred[i]; SS += sred2[i]; }
        float mu = S * (1.0f / CQ);
        float var = SS * (1.0f / CQ) - mu * mu;
        sred[0] = mu; sred2[0] = rsqrtf(var + 1e-5f);
    }
    __syncthreads();
    float mu = sred[0], rstd = sred2[0];
    #pragma unroll
    for (int j = 0; j < 3; j++) {
        int c = tid + j * 256;
        float v = (j == 0 ? v0 : j == 1 ? v1 : v2);
        float vn = (v - mu) * rstd * g[c] + b[c];
        bf16 h = __float2bfloat16(vn);
        g_anh[(size_t)row * CQ + c] = h;
        g_anl[(size_t)row * CQ + c] = __float2bfloat16(vn - __bfloat162float(h));
    }
}

// ================= weight transpose + split (all 5 weights) =================
__global__ void k_splitw(const float* w0, const float* w1, const float* w2,
                         const float* w3, const float* w4) {
    int which = blockIdx.y;
    const float* w = (which == 0) ? w0 : (which == 1) ? w1 : (which == 2) ? w2 :
                     (which == 3) ? w3 : w4;
    int idx = blockIdx.x * 256 + threadIdx.x;   // k*768 + n
    int k = idx / CQ, n = idx - k * CQ;
    float v = w[idx];
    bf16 h = __float2bfloat16(v);
    size_t off = (size_t)which * CQ * CQ + (size_t)n * CQ + k;
    g_wTh[off] = h;
    g_wTl[off] = __float2bfloat16(v - __bfloat162float(h));
}

// ================= pair bias (SIMT, DRAM-bound) =================
#define PB_SMEM_FLOATS (2*256*32 + 2048 + 32)
__global__ __launch_bounds__(256, 2)
void k_pair_bias(const float* __restrict__ z, const float* __restrict__ gz,
                 const float* __restrict__ bz, const float* __restrict__ wz) {
    extern __shared__ float sm[];
    float* zb    = sm;
    float* wps   = sm + 16384;
    float* cs_cb = wps + 2048;

    int tid = threadIdx.x;
    for (int i = tid; i < CZ * NH; i += 256) {
        int c = i >> 4, h = i & 15;
        wps[(c >> 1) * 32 + h * 2 + (c & 1)] = gz[c] * wz[c * NH + h];
    }
    __syncthreads();
    if (tid < 16) {
        float cs = 0.f, cb = 0.f;
        for (int c = 0; c < CZ; c++) {
            cs += wps[(c >> 1) * 32 + tid * 2 + (c & 1)];
            cb += bz[c] * wz[c * NH + tid];
        }
        cs_cb[tid] = cs; cs_cb[16 + tid] = cb;
    }
    __syncthreads();

    int tile = blockIdx.x;
    const float4* zg = (const float4*)(z + (size_t)tile * 256 * CZ);

    int srow[8], sf[8];
    #pragma unroll
    for (int j = 0; j < 8; j++) { int i = tid + j * 256; srow[j] = i >> 3; sf[j] = i & 7; }

    float4 pre[8];
    #pragma unroll
    for (int j = 0; j < 8; j++)
        pre[j] = zg[(size_t)srow[j] * 32 + sf[j]];

    ULL acc[NH];
    #pragma unroll
    for (int h = 0; h < NH; h++) acc[h] = 0ULL;
    ULL sum2 = 0ULL, ss2 = 0ULL;

    for (int c = 0; c < 4; c++) {
        float* buf = zb + (c & 1) * 8192;
        #pragma unroll
        for (int j = 0; j < 8; j++)
            *(float4*)(buf + srow[j] * 32 + ((sf[j] + srow[j]) & 7) * 4) = pre[j];
        __syncthreads();
        if (c < 3) {
            #pragma unroll
            for (int j = 0; j < 8; j++)
                pre[j] = zg[(size_t)srow[j] * 32 + (c + 1) * 8 + sf[j]];
        }
        #pragma unroll
        for (int j = 0; j < 8; j++) {
            int pos = (j + tid) & 7;
            float4 zv = *(const float4*)(buf + tid * 32 + pos * 4);
            ULL z01 = ((const ULL*)&zv)[0];
            ULL z23 = ((const ULL*)&zv)[1];
            sum2 = add2(sum2, add2(z01, z23));
            ss2  = fma2(z01, z01, fma2(z23, z23, ss2));
            int p0 = c * 16 + 2 * j;
            const float4* w0 = (const float4*)(wps + p0 * 32);
            const float4* w1 = (const float4*)(wps + p0 * 32 + 32);
            #pragma unroll
            for (int h2 = 0; h2 < 8; h2++) {
                float4 wa = w0[h2];
                float4 wb = w1[h2];
                acc[2*h2]     = fma2(z01, ((const ULL*)&wa)[0], acc[2*h2]);
                acc[2*h2 + 1] = fma2(z01, ((const ULL*)&wa)[1], acc[2*h2 + 1]);
                acc[2*h2]     = fma2(z23, ((const ULL*)&wb)[0], acc[2*h2]);
                acc[2*h2 + 1] = fma2(z23, ((const ULL*)&wb)[1], acc[2*h2 + 1]);
            }
        }
        __syncthreads();
    }

    float sum = lo2(sum2) + hi2(sum2);
    float ss  = lo2(ss2)  + hi2(ss2);
    float mu  = sum * (1.0f / CZ);
    float var = ss * (1.0f / CZ) - mu * mu;
    float rstd = rsqrtf(var + 1e-5f);

    float* outs = zb;
    #pragma unroll
    for (int h = 0; h < NH; h++) {
        float d = lo2(acc[h]) + hi2(acc[h]);
        outs[h * 256 + tid] = rstd * (d - mu * cs_cb[h]) + cs_cb[16 + h];
    }
    __syncthreads();
    #pragma unroll
    for (int it = 0; it < 4; it++) {
        int idx = tid + it * 256;
        int h = idx >> 6, j4 = idx & 63;
        float4 v = *(const float4*)(outs + h * 256 + j4 * 4);
        *(float4*)(g_bias + ((size_t)h << 20) + (size_t)tile * 256 + j4 * 4) = v;
    }
}

// ================= bf16x3 mma.sync GEMM core: CTA 128x64, warp 32x32 =================
#define ASTR 40   // bf16 stride for staged 32-k chunks
// smem: sAh[128*40] sAl[128*40] sBh[64*40] sBl[64*40] bf16 = 30720 B

__device__ __forceinline__ void gemm_core(
    const bf16* __restrict__ Ah, const bf16* __restrict__ Al, int lda,
    const bf16* __restrict__ Bh, const bf16* __restrict__ Bl, int ldb, int nrealB,
    int Kreal, int nchunks,
    bf16* sAh, bf16* sAl, bf16* sBh, bf16* sBl,
    float acc[2][4][4])
{
    int tid = threadIdx.x, lane = tid & 31, wid = tid >> 5;
    int wm = wid & 3, wn = wid >> 2;
    #pragma unroll
    for (int f = 0; f < 2; f++)
        #pragma unroll
        for (int nf = 0; nf < 4; nf++)
            #pragma unroll
            for (int i = 0; i < 4; i++) acc[f][nf][i] = 0.f;

    int sub = lane >> 3, rin = lane & 7;
    int rowoff = ((sub & 1) << 3) + rin;
    int koff = (sub >> 1) << 3;
    uint32_t uAh = s2u(sAh), uAl = s2u(sAl), uBh = s2u(sBh), uBl = s2u(sBl);

    for (int c = 0; c < nchunks; c++) {
        int k0 = c * 32;
        __syncthreads();
        #pragma unroll
        for (int j = 0; j < 2; j++) {
            int i = tid + j * 256;              // < 512
            int r = i >> 2, g = i & 3, k = k0 + g * 8;
            float4 vh = make_float4(0.f,0.f,0.f,0.f), vl = vh;
            if (k < Kreal) {
                vh = *(const float4*)(Ah + (size_t)r * lda + k);
                vl = *(const float4*)(Al + (size_t)r * lda + k);
            }
            *(float4*)(sAh + r * ASTR + g * 8) = vh;
            *(float4*)(sAl + r * ASTR + g * 8) = vl;
        }
        {
            int r = tid >> 2, g = tid & 3, k = k0 + g * 8;
            float4 vh = make_float4(0.f,0.f,0.f,0.f), vl = vh;
            if (r < nrealB && k < Kreal) {
                vh = *(const float4*)(Bh + (size_t)r * ldb + k);
                vl = *(const float4*)(Bl + (size_t)r * ldb + k);
            }
            *(float4*)(sBh + r * ASTR + g * 8) = vh;
            *(float4*)(sBl + r * ASTR + g * 8) = vl;
        }
        __syncthreads();

        #pragma unroll
        for (int s = 0; s < 2; s++) {
            if (k0 + s * 16 >= Kreal) break;
            uint32_t ah[2][4], al[2][4], bh[2][4], bl[2][4];
            #pragma unroll
            for (int f = 0; f < 2; f++) {
                uint32_t off = (uint32_t)((wm * 32 + f * 16 + rowoff) * ASTR + s * 16 + koff) * 2;
                ldsm4(ah[f], uAh + off);
                ldsm4(al[f], uAl + off);
            }
            #pragma unroll
            for (int g2 = 0; g2 < 2; g2++) {
                uint32_t off = (uint32_t)((wn * 32 + g2 * 16 + rowoff) * ASTR + s * 16 + koff) * 2;
                ldsm4(bh[g2], uBh + off);
                ldsm4(bl[g2], uBl + off);
            }
            #pragma unroll
            for (int f = 0; f < 2; f++)
                #pragma unroll
                for (int nf = 0; nf < 4; nf++) {
                    int g2 = nf >> 1, o = nf & 1;
                    mma16816(acc[f][nf], ah[f][0], ah[f][1], ah[f][2], ah[f][3],
                             bh[g2][o], bh[g2][2 + o]);
                    mma16816(acc[f][nf], ah[f][0], ah[f][1], ah[f][2], ah[f][3],
                             bl[g2][o], bl[g2][2 + o]);
                    mma16816(acc[f][nf], al[f][0], al[f][1], al[f][2], al[f][3],
                             bh[g2][o], bh[g2][2 + o]);
                }
        }
    }
}

#define GEMM_SHARED \
    __shared__ bf16 sAh[128 * ASTR], sAl[128 * ASTR]; \
    __shared__ bf16 sBh[64 * ASTR],  sBl[64 * ASTR]; \
    float acc[2][4][4]; \
    int lane = threadIdx.x & 31, wid = threadIdx.x >> 5; \
    int wm = wid & 3, wn = wid >> 2; \
    int erow = wm * 32 + (lane >> 2); \
    int ecol = wn * 32 + (lane & 3) * 2;

// ---- QKVG: an(1024x768) @ wT -> q,k,vT,gate ----
__global__ __launch_bounds__(256)
void k_gemm_qkvg(const float* __restrict__ bg) {
    GEMM_SHARED;
    int mode = blockIdx.z;
    int row0 = blockIdx.y * 128, n0 = blockIdx.x * 64;
    const bf16* Bh = g_wTh + (size_t)mode * CQ * CQ + (size_t)n0 * CQ;
    const bf16* Bl = g_wTl + (size_t)mode * CQ * CQ + (size_t)n0 * CQ;
    gemm_core(g_anh + (size_t)row0 * CQ, g_anl + (size_t)row0 * CQ, CQ,
              Bh, Bl, CQ, 64, CQ, CQ / 32, sAh, sAl, sBh, sBl, acc);
    #pragma unroll
    for (int f = 0; f < 2; f++)
        #pragma unroll
        for (int nf = 0; nf < 4; nf++)
            #pragma unroll
            for (int i = 0; i < 4; i++) {
                int row = row0 + erow + f * 16 + (i >> 1) * 8;
                int col = n0 + ecol + nf * 8 + (i & 1);
                float v = acc[f][nf][i];
                int h = col / HD, d = col - h * HD;
                if (mode == 0) {
                    float q = v * QSCALE;
                    bf16 hh = __float2bfloat16(q);
                    g_qh[((size_t)h * NTOK + row) * HD + d] = hh;
                    g_ql[((size_t)h * NTOK + row) * HD + d] = __float2bfloat16(q - __bfloat162float(hh));
                } else if (mode == 1) {
                    bf16 hh = __float2bfloat16(v);
                    g_kh[((size_t)h * NTOK + row) * HD + d] = hh;
                    g_kl[((size_t)h * NTOK + row) * HD + d] = __float2bfloat16(v - __bfloat162float(hh));
                } else if (mode == 2) {
                    bf16 hh = __float2bfloat16(v);
                    g_vth[((size_t)h * HD + d) * NTOK + row] = hh;
                    g_vtl[((size_t)h * HD + d) * NTOK + row] = __float2bfloat16(v - __bfloat162float(hh));
                } else {
                    g_gate[(size_t)row * HDQ + col] = 1.f / (1.f + __expf(-(v + bg[col])));
                }
            }
}

// ---- scores: S = Q K^T + bias + mask, in place over g_bias ----
__global__ __launch_bounds__(256)
void k_gemm_scores(const float* __restrict__ mask) {
    GEMM_SHARED;
    int h = blockIdx.z;
    int row0 = blockIdx.y * 128, n0 = blockIdx.x * 64;
    gemm_core(g_qh + ((size_t)h * NTOK + row0) * HD, g_ql + ((size_t)h * NTOK + row0) * HD, HD,
              g_kh + ((size_t)h * NTOK + n0) * HD,  g_kl + ((size_t)h * NTOK + n0) * HD,  HD,
              64, HD, 2, sAh, sAl, sBh, sBl, acc);
    float* bb = g_bias + ((size_t)h << 20);
    #pragma unroll
    for (int f = 0; f < 2; f++)
        #pragma unroll
        for (int nf = 0; nf < 4; nf++)
            #pragma unroll
            for (int i = 0; i < 4; i++) {
                int row = row0 + erow + f * 16 + (i >> 1) * 8;
                int col = n0 + ecol + nf * 8 + (i & 1);
                float mr = __ldg(mask + row), mc = __ldg(mask + col);
                bb[(size_t)row * NTOK + col] += acc[f][nf][i] + 1e9f * (mr * mc - 1.f);
            }
}

// ---- softmax -> normalized bf16 splits ----
__global__ void k_softmax(int dummy) {
    int row = blockIdx.x, h = blockIdx.y, tid = threadIdx.x;
    const float* p = g_bias + ((size_t)h << 20) + (size_t)row * NTOK + tid * 4;
    float4 v = *(const float4*)p;
    __shared__ float red[8], red2[8];
    float m = fmaxf(fmaxf(v.x, v.y), fmaxf(v.z, v.w));
    #pragma unroll
    for (int o = 16; o; o >>= 1) m = fmaxf(m, __shfl_xor_sync(0xffffffffu, m, o));
    if ((tid & 31) == 0) red[tid >> 5] = m;
    __syncthreads();
    m = red[tid & 7];
    #pragma unroll
    for (int o = 4; o; o >>= 1) m = fmaxf(m, __shfl_xor_sync(0xffffffffu, m, o));

    v.x = __expf(v.x - m); v.y = __expf(v.y - m);
    v.z = __expf(v.z - m); v.w = __expf(v.w - m);
    float s = v.x + v.y + v.z + v.w;
    #pragma unroll
    for (int o = 16; o; o >>= 1) s += __shfl_xor_sync(0xffffffffu, s, o);
    if ((tid & 31) == 0) red2[tid >> 5] = s;
    __syncthreads();
    s = red2[tid & 7];
    #pragma unroll
    for (int o = 4; o; o >>= 1) s += __shfl_xor_sync(0xffffffffu, s, o);
    float inv = 1.f / s;
    size_t base = ((size_t)h << 20) + (size_t)row * NTOK + tid * 4;
    float pv[4] = {v.x * inv, v.y * inv, v.z * inv, v.w * inv};
    #pragma unroll
    for (int j = 0; j < 4; j++) {
        bf16 hh = __float2bfloat16(pv[j]);
        g_ph[base + j] = hh;
        g_pl[base + j] = __float2bfloat16(pv[j] - __bfloat162float(hh));
    }
}

// ---- PV: O = P @ V (vT is [d][tok] = N x K layout), gated ----
__global__ __launch_bounds__(256)
void k_gemm_pv(int dummy) {
    GEMM_SHARED;
    int h = blockIdx.z;
    int row0 = blockIdx.y * 128;
    gemm_core(g_ph + ((size_t)h << 20) + (size_t)row0 * NTOK,
              g_pl + ((size_t)h << 20) + (size_t)row0 * NTOK, NTOK,
              g_vth + (size_t)h * HD * NTOK, g_vtl + (size_t)h * HD * NTOK, NTOK,
              HD, NTOK, NTOK / 32, sAh, sAl, sBh, sBl, acc);
    #pragma unroll
    for (int f = 0; f < 2; f++)
        #pragma unroll
        for (int nf = 0; nf < 4; nf++)
            #pragma unroll
            for (int i = 0; i < 4; i++) {
                int row = row0 + erow + f * 16 + (i >> 1) * 8;
                int col = ecol + nf * 8 + (i & 1);
                if (col < HD) {
                    size_t idx = (size_t)row * HDQ + h * HD + col;
                    float o = acc[f][nf][i] * g_gate[idx];
                    bf16 hh = __float2bfloat16(o);
                    g_ogh[idx] = hh;
                    g_ogl[idx] = __float2bfloat16(o - __bfloat162float(hh));
                }
            }
}

// ---- out projection ----
__global__ __launch_bounds__(256)
void k_gemm_out(const float* __restrict__ bo, float* __restrict__ out) {
    GEMM_SHARED;
    int row0 = blockIdx.y * 128, n0 = blockIdx.x * 64;
    const bf16* Bh = g_wTh + 4ull * CQ * CQ + (size_t)n0 * CQ;
    const bf16* Bl = g_wTl + 4ull * CQ * CQ + (size_t)n0 * CQ;
    gemm_core(g_ogh + (size_t)row0 * CQ, g_ogl + (size_t)row0 * CQ, CQ,
              Bh, Bl, CQ, 64, CQ, CQ / 32, sAh, sAl, sBh, sBl, acc);
    #pragma unroll
    for (int f = 0; f < 2; f++)
        #pragma unroll
        for (int nf = 0; nf < 4; nf++)
            #pragma unroll
            for (int i = 0; i < 4; i++) {
                int row = row0 + erow + f * 16 + (i >> 1) * 8;
                int col = n0 + ecol + nf * 8 + (i & 1);
                out[(size_t)row * CQ + col] = acc[f][nf][i] + __ldg(bo + col);
            }
}

// ================= launch =================
extern "C" void kernel_launch(void* const* d_in, const int* in_sizes, int n_in,
                              void* d_out, int out_size) {
    const float* a    = (const float*)d_in[0];
    const float* z    = (const float*)d_in[1];
    const float* mask = (const float*)d_in[2];
    const float* ga   = (const float*)d_in[3];
    const float* ba   = (const float*)d_in[4];
    const float* gz   = (const float*)d_in[5];
    const float* bz   = (const float*)d_in[6];
    const float* wz   = (const float*)d_in[7];
    const float* wq   = (const float*)d_in[8];
    const float* wk   = (const float*)d_in[9];
    const float* wv   = (const float*)d_in[10];
    const float* wg   = (const float*)d_in[11];
    const float* bg   = (const float*)d_in[12];
    const float* wo   = (const float*)d_in[13];
    const float* bo   = (const float*)d_in[14];
    float* out = (float*)d_out;

    cudaFuncSetAttribute(k_pair_bias, cudaFuncAttributeMaxDynamicSharedMemorySize, PB_SMEM_FLOATS * 4);

    k_pair_bias<<<4096, 256, PB_SMEM_FLOATS * 4>>>(z, gz, bz, wz);
    k_ln_a<<<1024, 256>>>(a, ga, ba);
    k_splitw<<<dim3(CQ * CQ / 256, 5), 256>>>(wq, wk, wv, wg, wo);

    k_gemm_qkvg<<<dim3(12, 8, 4), 256>>>(bg);
    k_gemm_scores<<<dim3(16, 8, NH), 256>>>(mask);
    k_softmax<<<dim3(NTOK, NH), 256>>>(0);
    k_gemm_pv<<<dim3(1, 8, NH), 256>>>(0);
    k_gemm_out<<<dim3(12, 8), 256>>>(bo, out);
}

// round 8
// speedup vs baseline: 1.2868x; 1.0665x over previous
#include <cuda_runtime.h>
#include <cuda_bf16.h>
#include <cstdint>

typedef unsigned long long ULL;
typedef __nv_bfloat16 bf16;

#define NTOK 1024
#define CQ   768
#define CZ   128
#define NH   16
#define HD   48
#define HDQ  768
#define QSCALE 0.14433756729740643f  // 1/sqrt(48)

// ================= f32x2 helpers (pair_bias) =================
__device__ __forceinline__ ULL fma2(ULL a, ULL b, ULL c) {
    ULL d; asm("fma.rn.f32x2 %0, %1, %2, %3;" : "=l"(d) : "l"(a), "l"(b), "l"(c)); return d;
}
__device__ __forceinline__ ULL add2(ULL a, ULL b) {
    ULL d; asm("add.rn.f32x2 %0, %1, %2;" : "=l"(d) : "l"(a), "l"(b)); return d;
}
__device__ __forceinline__ float lo2(ULL u){ return __uint_as_float((unsigned)u); }
__device__ __forceinline__ float hi2(ULL u){ return __uint_as_float((unsigned)(u >> 32)); }

// ================= mma.sync helpers =================
__device__ __forceinline__ uint32_t s2u(const void* p){
    uint32_t a; asm("{ .reg .u64 t; cvta.to.shared.u64 t, %1; cvt.u32.u64 %0, t; }" : "=r"(a) : "l"(p));
    return a;
}
__device__ __forceinline__ void ldsm4(uint32_t* r, uint32_t addr){
    asm volatile("ldmatrix.sync.aligned.m8n8.x4.shared.b16 {%0,%1,%2,%3}, [%4];"
        : "=r"(r[0]), "=r"(r[1]), "=r"(r[2]), "=r"(r[3]) : "r"(addr));
}
__device__ __forceinline__ void mma16816(float* c, uint32_t a0, uint32_t a1, uint32_t a2, uint32_t a3,
                                         uint32_t b0, uint32_t b1){
    asm volatile("mma.sync.aligned.m16n8k16.row.col.f32.bf16.bf16.f32 "
        "{%0,%1,%2,%3}, {%4,%5,%6,%7}, {%8,%9}, {%0,%1,%2,%3};"
        : "+f"(c[0]), "+f"(c[1]), "+f"(c[2]), "+f"(c[3])
        : "r"(a0), "r"(a1), "r"(a2), "r"(a3), "r"(b0), "r"(b1));
}
__device__ __forceinline__ void cpa16(uint32_t dst, const void* src, bool p){
    int sz = p ? 16 : 0;
    asm volatile("cp.async.cg.shared.global [%0], [%1], 16, %2;"
        :: "r"(dst), "l"(src), "r"(sz) : "memory");
}
#define CP_COMMIT() asm volatile("cp.async.commit_group;" ::: "memory")
#define CP_WAIT(N)  asm volatile("cp.async.wait_group %0;" :: "n"(N) : "memory")

// ================= scratch =================
__device__ float g_bias[(size_t)NH * NTOK * NTOK];
__device__ bf16  g_anh[NTOK * CQ], g_anl[NTOK * CQ];
__device__ bf16  g_wTh[5u * CQ * CQ], g_wTl[5u * CQ * CQ];   // [n][k]
__device__ bf16  g_qh[NH * NTOK * HD], g_ql[NH * NTOK * HD];
__device__ bf16  g_kh[NH * NTOK * HD], g_kl[NH * NTOK * HD];
__device__ bf16  g_vth[NH * HD * NTOK], g_vtl[NH * HD * NTOK]; // [h][d][tok]
__device__ bf16  g_ph[(size_t)NH * NTOK * NTOK], g_pl[(size_t)NH * NTOK * NTOK];
__device__ float g_gate[NTOK * HDQ];
__device__ bf16  g_ogh[NTOK * HDQ], g_ogl[NTOK * HDQ];

// ================= LayerNorm of a -> bf16 splits =================
__global__ void k_ln_a(const float* __restrict__ a, const float* __restrict__ g,
                       const float* __restrict__ b) {
    int row = blockIdx.x, tid = threadIdx.x;
    const float* x = a + (size_t)row * CQ;
    float v0 = x[tid], v1 = x[tid + 256], v2 = x[tid + 512];
    float s = v0 + v1 + v2;
    float ss = v0*v0 + v1*v1 + v2*v2;
    __shared__ float sred[8], sred2[8];
    #pragma unroll
    for (int o = 16; o; o >>= 1) {
        s  += __shfl_xor_sync(0xffffffffu, s, o);
        ss += __shfl_xor_sync(0xffffffffu, ss, o);
    }
    if ((tid & 31) == 0) { sred[tid >> 5] = s; sred2[tid >> 5] = ss; }
    __syncthreads();
    if (tid == 0) {
        float S = 0, SS = 0;
        for (int i = 0; i < 8; i++) { S += sred[i]; SS += sred2[i]; }
        float mu = S * (1.0f / CQ);
        float var = SS * (1.0f / CQ) - mu * mu;
        sred[0] = mu; sred2[0] = rsqrtf(var + 1e-5f);
    }
    __syncthreads();
    float mu = sred[0], rstd = sred2[0];
    #pragma unroll
    for (int j = 0; j < 3; j++) {
        int c = tid + j * 256;
        float v = (j == 0 ? v0 : j == 1 ? v1 : v2);
        float vn = (v - mu) * rstd * g[c] + b[c];
        bf16 h = __float2bfloat16(vn);
        g_anh[(size_t)row * CQ + c] = h;
        g_anl[(size_t)row * CQ + c] = __float2bfloat16(vn - __bfloat162float(h));
    }
}

// ================= weight transpose + split =================
__global__ void k_splitw(const float* w0, const float* w1, const float* w2,
                         const float* w3, const float* w4) {
    int which = blockIdx.y;
    const float* w = (which == 0) ? w0 : (which == 1) ? w1 : (which == 2) ? w2 :
                     (which == 3) ? w3 : w4;
    int idx = blockIdx.x * 256 + threadIdx.x;   // k*768 + n
    int k = idx / CQ, n = idx - k * CQ;
    float v = w[idx];
    bf16 h = __float2bfloat16(v);
    size_t off = (size_t)which * CQ * CQ + (size_t)n * CQ + k;
    g_wTh[off] = h;
    g_wTl[off] = __float2bfloat16(v - __bfloat162float(h));
}

// ================= pair bias (SIMT, DRAM-bound) =================
#define PB_SMEM_FLOATS (2*256*32 + 2048 + 32)
__global__ __launch_bounds__(256, 2)
void k_pair_bias(const float* __restrict__ z, const float* __restrict__ gz,
                 const float* __restrict__ bz, const float* __restrict__ wz) {
    extern __shared__ float sm[];
    float* zb    = sm;
    float* wps   = sm + 16384;
    float* cs_cb = wps + 2048;

    int tid = threadIdx.x;
    for (int i = tid; i < CZ * NH; i += 256) {
        int c = i >> 4, h = i & 15;
        wps[(c >> 1) * 32 + h * 2 + (c & 1)] = gz[c] * wz[c * NH + h];
    }
    __syncthreads();
    if (tid < 16) {
        float cs = 0.f, cb = 0.f;
        for (int c = 0; c < CZ; c++) {
            cs += wps[(c >> 1) * 32 + tid * 2 + (c & 1)];
            cb += bz[c] * wz[c * NH + tid];
        }
        cs_cb[tid] = cs; cs_cb[16 + tid] = cb;
    }
    __syncthreads();

    int tile = blockIdx.x;
    const float4* zg = (const float4*)(z + (size_t)tile * 256 * CZ);

    int srow[8], sf[8];
    #pragma unroll
    for (int j = 0; j < 8; j++) { int i = tid + j * 256; srow[j] = i >> 3; sf[j] = i & 7; }

    float4 pre[8];
    #pragma unroll
    for (int j = 0; j < 8; j++)
        pre[j] = zg[(size_t)srow[j] * 32 + sf[j]];

    ULL acc[NH];
    #pragma unroll
    for (int h = 0; h < NH; h++) acc[h] = 0ULL;
    ULL sum2 = 0ULL, ss2 = 0ULL;

    for (int c = 0; c < 4; c++) {
        float* buf = zb + (c & 1) * 8192;
        #pragma unroll
        for (int j = 0; j < 8; j++)
            *(float4*)(buf + srow[j] * 32 + ((sf[j] + srow[j]) & 7) * 4) = pre[j];
        __syncthreads();
        if (c < 3) {
            #pragma unroll
            for (int j = 0; j < 8; j++)
                pre[j] = zg[(size_t)srow[j] * 32 + (c + 1) * 8 + sf[j]];
        }
        #pragma unroll
        for (int j = 0; j < 8; j++) {
            int pos = (j + tid) & 7;
            float4 zv = *(const float4*)(buf + tid * 32 + pos * 4);
            ULL z01 = ((const ULL*)&zv)[0];
            ULL z23 = ((const ULL*)&zv)[1];
            sum2 = add2(sum2, add2(z01, z23));
            ss2  = fma2(z01, z01, fma2(z23, z23, ss2));
            int p0 = c * 16 + 2 * j;
            const float4* w0 = (const float4*)(wps + p0 * 32);
            const float4* w1 = (const float4*)(wps + p0 * 32 + 32);
            #pragma unroll
            for (int h2 = 0; h2 < 8; h2++) {
                float4 wa = w0[h2];
                float4 wb = w1[h2];
                acc[2*h2]     = fma2(z01, ((const ULL*)&wa)[0], acc[2*h2]);
                acc[2*h2 + 1] = fma2(z01, ((const ULL*)&wa)[1], acc[2*h2 + 1]);
                acc[2*h2]     = fma2(z23, ((const ULL*)&wb)[0], acc[2*h2]);
                acc[2*h2 + 1] = fma2(z23, ((const ULL*)&wb)[1], acc[2*h2 + 1]);
            }
        }
        __syncthreads();
    }

    float sum = lo2(sum2) + hi2(sum2);
    float ss  = lo2(ss2)  + hi2(ss2);
    float mu  = sum * (1.0f / CZ);
    float var = ss * (1.0f / CZ) - mu * mu;
    float rstd = rsqrtf(var + 1e-5f);

    float* outs = zb;
    #pragma unroll
    for (int h = 0; h < NH; h++) {
        float d = lo2(acc[h]) + hi2(acc[h]);
        outs[h * 256 + tid] = rstd * (d - mu * cs_cb[h]) + cs_cb[16 + h];
    }
    __syncthreads();
    #pragma unroll
    for (int it = 0; it < 4; it++) {
        int idx = tid + it * 256;
        int h = idx >> 6, j4 = idx & 63;
        float4 v = *(const float4*)(outs + h * 256 + j4 * 4);
        *(float4*)(g_bias + ((size_t)h << 20) + (size_t)tile * 256 + j4 * 4) = v;
    }
}

// ================= bf16x3 mma.sync GEMM core, 2-stage cp.async pipeline =================
#define ASTR 40
// stage layout (bytes): Ah 0 (10240), Al 10240 (10240), Bh 20480 (5120), Bl 25600 (5120)
#define ST_AL 10240u
#define ST_BH 20480u
#define ST_BL 25600u
#define STAGE_BYTES 30720u
#define GEMM_SMEM (2 * STAGE_BYTES)

__device__ __forceinline__ void stage_chunk(
    const bf16* __restrict__ Ah, const bf16* __restrict__ Al, int lda,
    const bf16* __restrict__ Bh, const bf16* __restrict__ Bl, int ldb, int nrealB,
    int k0, int Kreal, uint32_t sb)
{
    int tid = threadIdx.x;
    #pragma unroll
    for (int j = 0; j < 2; j++) {
        int i = tid + j * 256;                 // < 512
        int r = i >> 2, g = i & 3, k = k0 + g * 8;
        bool p = (k < Kreal);
        const bf16* sa = p ? (Ah + (size_t)r * lda + k) : Ah;
        const bf16* sl = p ? (Al + (size_t)r * lda + k) : Al;
        uint32_t doff = (uint32_t)(r * ASTR + g * 8) * 2;
        cpa16(sb + doff, sa, p);
        cpa16(sb + ST_AL + doff, sl, p);
    }
    {
        int r = tid >> 2, g = tid & 3, k = k0 + g * 8;
        bool p = (r < nrealB) && (k < Kreal);
        const bf16* sbh = p ? (Bh + (size_t)r * ldb + k) : Bh;
        const bf16* sbl = p ? (Bl + (size_t)r * ldb + k) : Bl;
        uint32_t doff = (uint32_t)(r * ASTR + g * 8) * 2;
        cpa16(sb + ST_BH + doff, sbh, p);
        cpa16(sb + ST_BL + doff, sbl, p);
    }
    CP_COMMIT();
}

__device__ __forceinline__ void gemm_core(
    const bf16* __restrict__ Ah, const bf16* __restrict__ Al, int lda,
    const bf16* __restrict__ Bh, const bf16* __restrict__ Bl, int ldb, int nrealB,
    int Kreal, int nchunks, uint32_t sbase, float acc[2][4][4])
{
    int lane = threadIdx.x & 31, wid = threadIdx.x >> 5;
    int wm = wid & 3, wn = wid >> 2;
    #pragma unroll
    for (int f = 0; f < 2; f++)
        #pragma unroll
        for (int nf = 0; nf < 4; nf++)
            #pragma unroll
            for (int i = 0; i < 4; i++) acc[f][nf][i] = 0.f;

    int sub = lane >> 3, rin = lane & 7;
    int rowoff = ((sub & 1) << 3) + rin;
    int koff = (sub >> 1) << 3;

    stage_chunk(Ah, Al, lda, Bh, Bl, ldb, nrealB, 0, Kreal, sbase);

    for (int c = 0; c < nchunks; c++) {
        uint32_t sb = sbase + (uint32_t)(c & 1) * STAGE_BYTES;
        if (c + 1 < nchunks) {
            stage_chunk(Ah, Al, lda, Bh, Bl, ldb, nrealB, (c + 1) * 32, Kreal,
                        sbase + (uint32_t)((c + 1) & 1) * STAGE_BYTES);
            CP_WAIT(1);
        } else {
            CP_WAIT(0);
        }
        __syncthreads();

        #pragma unroll
        for (int s = 0; s < 2; s++) {
            uint32_t ah[2][4], al[2][4], bh[2][4], bl[2][4];
            #pragma unroll
            for (int f = 0; f < 2; f++) {
                uint32_t off = (uint32_t)((wm * 32 + f * 16 + rowoff) * ASTR + s * 16 + koff) * 2;
                ldsm4(ah[f], sb + off);
                ldsm4(al[f], sb + ST_AL + off);
            }
            #pragma unroll
            for (int g2 = 0; g2 < 2; g2++) {
                uint32_t off = (uint32_t)((wn * 32 + g2 * 16 + rowoff) * ASTR + s * 16 + koff) * 2;
                ldsm4(bh[g2], sb + ST_BH + off);
                ldsm4(bl[g2], sb + ST_BL + off);
            }
            #pragma unroll
            for (int f = 0; f < 2; f++)
                #pragma unroll
                for (int nf = 0; nf < 4; nf++) {
                    int g2 = nf >> 1, o = nf & 1;
                    mma16816(acc[f][nf], ah[f][0], ah[f][1], ah[f][2], ah[f][3],
                             bh[g2][o], bh[g2][2 + o]);
                    mma16816(acc[f][nf], ah[f][0], ah[f][1], ah[f][2], ah[f][3],
                             bl[g2][o], bl[g2][2 + o]);
                    mma16816(acc[f][nf], al[f][0], al[f][1], al[f][2], al[f][3],
                             bh[g2][o], bh[g2][2 + o]);
                }
        }
        __syncthreads();
    }
}

#define GEMM_SHARED \
    extern __shared__ char dsm[]; \
    uint32_t sbase = s2u(dsm); \
    float acc[2][4][4]; \
    int lane = threadIdx.x & 31, wid = threadIdx.x >> 5; \
    int wm = wid & 3, wn = wid >> 2; \
    int erow = wm * 32 + (lane >> 2); \
    int ecol = wn * 32 + (lane & 3) * 2;

// ---- QKVG ----
__global__ __launch_bounds__(256)
void k_gemm_qkvg(const float* __restrict__ bg) {
    GEMM_SHARED;
    int mode = blockIdx.z;
    int row0 = blockIdx.y * 128, n0 = blockIdx.x * 64;
    const bf16* Bh = g_wTh + (size_t)mode * CQ * CQ + (size_t)n0 * CQ;
    const bf16* Bl = g_wTl + (size_t)mode * CQ * CQ + (size_t)n0 * CQ;
    gemm_core(g_anh + (size_t)row0 * CQ, g_anl + (size_t)row0 * CQ, CQ,
              Bh, Bl, CQ, 64, CQ, CQ / 32, sbase, acc);
    #pragma unroll
    for (int f = 0; f < 2; f++)
        #pragma unroll
        for (int nf = 0; nf < 4; nf++)
            #pragma unroll
            for (int i = 0; i < 4; i++) {
                int row = row0 + erow + f * 16 + (i >> 1) * 8;
                int col = n0 + ecol + nf * 8 + (i & 1);
                float v = acc[f][nf][i];
                int h = col / HD, d = col - h * HD;
                if (mode == 0) {
                    float q = v * QSCALE;
                    bf16 hh = __float2bfloat16(q);
                    g_qh[((size_t)h * NTOK + row) * HD + d] = hh;
                    g_ql[((size_t)h * NTOK + row) * HD + d] = __float2bfloat16(q - __bfloat162float(hh));
                } else if (mode == 1) {
                    bf16 hh = __float2bfloat16(v);
                    g_kh[((size_t)h * NTOK + row) * HD + d] = hh;
                    g_kl[((size_t)h * NTOK + row) * HD + d] = __float2bfloat16(v - __bfloat162float(hh));
                } else if (mode == 2) {
                    bf16 hh = __float2bfloat16(v);
                    g_vth[((size_t)h * HD + d) * NTOK + row] = hh;
                    g_vtl[((size_t)h * HD + d) * NTOK + row] = __float2bfloat16(v - __bfloat162float(hh));
                } else {
                    g_gate[(size_t)row * HDQ + col] = 1.f / (1.f + __expf(-(v + bg[col])));
                }
            }
}

// ---- scores ----
__global__ __launch_bounds__(256)
void k_gemm_scores(const float* __restrict__ mask) {
    GEMM_SHARED;
    int h = blockIdx.z;
    int row0 = blockIdx.y * 128, n0 = blockIdx.x * 64;
    gemm_core(g_qh + ((size_t)h * NTOK + row0) * HD, g_ql + ((size_t)h * NTOK + row0) * HD, HD,
              g_kh + ((size_t)h * NTOK + n0) * HD,  g_kl + ((size_t)h * NTOK + n0) * HD,  HD,
              64, HD, 2, sbase, acc);
    float* bb = g_bias + ((size_t)h << 20);
    #pragma unroll
    for (int f = 0; f < 2; f++)
        #pragma unroll
        for (int nf = 0; nf < 4; nf++)
            #pragma unroll
            for (int i = 0; i < 4; i++) {
                int row = row0 + erow + f * 16 + (i >> 1) * 8;
                int col = n0 + ecol + nf * 8 + (i & 1);
                float mr = __ldg(mask + row), mc = __ldg(mask + col);
                bb[(size_t)row * NTOK + col] += acc[f][nf][i] + 1e9f * (mr * mc - 1.f);
            }
}

// ---- softmax -> normalized bf16 splits ----
__global__ void k_softmax(int dummy) {
    int row = blockIdx.x, h = blockIdx.y, tid = threadIdx.x;
    const float* p = g_bias + ((size_t)h << 20) + (size_t)row * NTOK + tid * 4;
    float4 v = *(const float4*)p;
    __shared__ float red[8], red2[8];
    float m = fmaxf(fmaxf(v.x, v.y), fmaxf(v.z, v.w));
    #pragma unroll
    for (int o = 16; o; o >>= 1) m = fmaxf(m, __shfl_xor_sync(0xffffffffu, m, o));
    if ((tid & 31) == 0) red[tid >> 5] = m;
    __syncthreads();
    m = red[tid & 7];
    #pragma unroll
    for (int o = 4; o; o >>= 1) m = fmaxf(m, __shfl_xor_sync(0xffffffffu, m, o));

    v.x = __expf(v.x - m); v.y = __expf(v.y - m);
    v.z = __expf(v.z - m); v.w = __expf(v.w - m);
    float s = v.x + v.y + v.z + v.w;
    #pragma unroll
    for (int o = 16; o; o >>= 1) s += __shfl_xor_sync(0xffffffffu, s, o);
    if ((tid & 31) == 0) red2[tid >> 5] = s;
    __syncthreads();
    s = red2[tid & 7];
    #pragma unroll
    for (int o = 4; o; o >>= 1) s += __shfl_xor_sync(0xffffffffu, s, o);
    float inv = 1.f / s;
    size_t base = ((size_t)h << 20) + (size_t)row * NTOK + tid * 4;
    float pv[4] = {v.x * inv, v.y * inv, v.z * inv, v.w * inv};
    #pragma unroll
    for (int j = 0; j < 4; j++) {
        bf16 hh = __float2bfloat16(pv[j]);
        g_ph[base + j] = hh;
        g_pl[base + j] = __float2bfloat16(pv[j] - __bfloat162float(hh));
    }
}

// ---- PV ----
__global__ __launch_bounds__(256)
void k_gemm_pv(int dummy) {
    GEMM_SHARED;
    int h = blockIdx.z;
    int row0 = blockIdx.y * 128;
    gemm_core(g_ph + ((size_t)h << 20) + (size_t)row0 * NTOK,
              g_pl + ((size_t)h << 20) + (size_t)row0 * NTOK, NTOK,
              g_vth + (size_t)h * HD * NTOK, g_vtl + (size_t)h * HD * NTOK, NTOK,
              HD, NTOK, NTOK / 32, sbase, acc);
    #pragma unroll
    for (int f = 0; f < 2; f++)
        #pragma unroll
        for (int nf = 0; nf < 4; nf++)
            #pragma unroll
            for (int i = 0; i < 4; i++) {
                int row = row0 + erow + f * 16 + (i >> 1) * 8;
                int col = ecol + nf * 8 + (i & 1);
                if (col < HD) {
                    size_t idx = (size_t)row * HDQ + h * HD + col;
                    float o = acc[f][nf][i] * g_gate[idx];
                    bf16 hh = __float2bfloat16(o);
                    g_ogh[idx] = hh;
                    g_ogl[idx] = __float2bfloat16(o - __bfloat162float(hh));
                }
            }
}

// ---- out projection ----
__global__ __launch_bounds__(256)
void k_gemm_out(const float* __restrict__ bo, float* __restrict__ out) {
    GEMM_SHARED;
    int row0 = blockIdx.y * 128, n0 = blockIdx.x * 64;
    const bf16* Bh = g_wTh + 4ull * CQ * CQ + (size_t)n0 * CQ;
    const bf16* Bl = g_wTl + 4ull * CQ * CQ + (size_t)n0 * CQ;
    gemm_core(g_ogh + (size_t)row0 * CQ, g_ogl + (size_t)row0 * CQ, CQ,
              Bh, Bl, CQ, 64, CQ, CQ / 32, sbase, acc);
    #pragma unroll
    for (int f = 0; f < 2; f++)
        #pragma unroll
        for (int nf = 0; nf < 4; nf++)
            #pragma unroll
            for (int i = 0; i < 4; i++) {
                int row = row0 + erow + f * 16 + (i >> 1) * 8;
                int col = n0 + ecol + nf * 8 + (i & 1);
                out[(size_t)row * CQ + col] = acc[f][nf][i] + __ldg(bo + col);
            }
}

// ================= launch =================
extern "C" void kernel_launch(void* const* d_in, const int* in_sizes, int n_in,
                              void* d_out, int out_size) {
    const float* a    = (const float*)d_in[0];
    const float* z    = (const float*)d_in[1];
    const float* mask = (const float*)d_in[2];
    const float* ga   = (const float*)d_in[3];
    const float* ba   = (const float*)d_in[4];
    const float* gz   = (const float*)d_in[5];
    const float* bz   = (const float*)d_in[6];
    const float* wz   = (const float*)d_in[7];
    const float* wq   = (const float*)d_in[8];
    const float* wk   = (const float*)d_in[9];
    const float* wv   = (const float*)d_in[10];
    const float* wg   = (const float*)d_in[11];
    const float* bg   = (const float*)d_in[12];
    const float* wo   = (const float*)d_in[13];
    const float* bo   = (const float*)d_in[14];
    float* out = (float*)d_out;

    cudaFuncSetAttribute(k_pair_bias,   cudaFuncAttributeMaxDynamicSharedMemorySize, PB_SMEM_FLOATS * 4);
    cudaFuncSetAttribute(k_gemm_qkvg,   cudaFuncAttributeMaxDynamicSharedMemorySize, GEMM_SMEM);
    cudaFuncSetAttribute(k_gemm_scores, cudaFuncAttributeMaxDynamicSharedMemorySize, GEMM_SMEM);
    cudaFuncSetAttribute(k_gemm_pv,     cudaFuncAttributeMaxDynamicSharedMemorySize, GEMM_SMEM);
    cudaFuncSetAttribute(k_gemm_out,    cudaFuncAttributeMaxDynamicSharedMemorySize, GEMM_SMEM);

    k_pair_bias<<<4096, 256, PB_SMEM_FLOATS * 4>>>(z, gz, bz, wz);
    k_ln_a<<<1024, 256>>>(a, ga, ba);
    k_splitw<<<dim3(CQ * CQ / 256, 5), 256>>>(wq, wk, wv, wg, wo);

    k_gemm_qkvg<<<dim3(12, 8, 4), 256, GEMM_SMEM>>>(bg);
    k_gemm_scores<<<dim3(16, 8, NH), 256, GEMM_SMEM>>>(mask);
    k_softmax<<<dim3(NTOK, NH), 256>>>(0);
    k_gemm_pv<<<dim3(1, 8, NH), 256, GEMM_SMEM>>>(0);
    k_gemm_out<<<dim3(12, 8), 256, GEMM_SMEM>>>(bo, out);
}